// round 3
// baseline (speedup 1.0000x reference)
#include <cuda_runtime.h>

#define D 64
#define H 256
#define ROWS 128
#define THREADS 128
#define XPAD 65   // padded row stride in smem floats -> conflict-free per-thread row reads

__device__ __forceinline__ void ffma2(unsigned long long& d,
                                      unsigned long long a,
                                      unsigned long long b) {
    // packed 2xfp32 FMA (Blackwell f32x2 pipe)
    asm("fma.rn.f32x2 %0, %1, %2, %0;" : "+l"(d) : "l"(a), "l"(b));
}

__device__ __forceinline__ unsigned long long fadd2(unsigned long long a,
                                                    unsigned long long b) {
    unsigned long long d;
    asm("add.rn.f32x2 %0, %1, %2;" : "=l"(d) : "l"(a), "l"(b));
    return d;
}

__device__ __forceinline__ unsigned long long pack2(float lo, float hi) {
    unsigned long long d;
    asm("mov.b64 %0, {%1, %2};" : "=l"(d) : "f"(lo), "f"(hi));
    return d;
}

__device__ __forceinline__ void unpack2(unsigned long long v, float& lo, float& hi) {
    asm("mov.b64 {%0, %1}, %2;" : "=f"(lo), "=f"(hi) : "l"(v));
}

__device__ __forceinline__ float ex2_approx(float x) {
    float r;
    asm("ex2.approx.f32 %0, %1;" : "=f"(r) : "f"(x));
    return r;
}

__global__ void __launch_bounds__(THREADS, 2)
rbf_svm_kernel(const float* __restrict__ X,
               const float* __restrict__ C,
               const float* __restrict__ w,
               const float* __restrict__ bias,
               float* __restrict__ out) {
    extern __shared__ float smem[];
    float* c_s   = smem;              // H*D center values
    float* c2l_s = c_s + H * D;       // H   (||c||^2 * log2e)
    float* w_s   = c2l_s + H;         // H
    float* x_s   = w_s + H;           // ROWS * XPAD staging tile

    const int tid = threadIdx.x;
    const float LOG2E = 1.4426950408889634f;

    // ---- stage centers (coalesced float4) ----
    {
        const float4* src = (const float4*)C;
        float4* dst = (float4*)c_s;
        for (int i = tid; i < H * D / 4; i += THREADS) dst[i] = src[i];
    }
    for (int i = tid; i < H; i += THREADS) w_s[i] = w[i];

    // ---- stage this block's X tile (coalesced) into padded smem ----
    {
        const float4* src = (const float4*)(X + (size_t)blockIdx.x * ROWS * D);
        for (int i = tid; i < ROWS * D / 4; i += THREADS) {
            float4 v = src[i];
            int r = i >> 4;             // i / (D/4)
            int c = (i & 15) << 2;
            float* p = x_s + r * XPAD + c;
            p[0] = v.x; p[1] = v.y; p[2] = v.z; p[3] = v.w;
        }
    }
    __syncthreads();

    // ---- per-center squared norm, pre-scaled by log2e ----
    for (int h = tid; h < H; h += THREADS) {
        const float* cp = c_s + h * D;
        float s = 0.f;
        #pragma unroll
        for (int d = 0; d < D; d++) s = fmaf(cp[d], cp[d], s);
        c2l_s[h] = s * LOG2E;
    }
    __syncthreads();

    // ---- each thread owns one X row, packed into f32x2 registers ----
    unsigned long long xr[D / 2];
    float x2 = 0.f;
    {
        const float* p = x_s + tid * XPAD;
        #pragma unroll
        for (int j = 0; j < D / 2; j++) {
            float a = p[2 * j], b = p[2 * j + 1];
            x2 = fmaf(a, a, x2);
            x2 = fmaf(b, b, x2);
            xr[j] = pack2(a, b);
        }
    }
    const float x2l = x2 * LOG2E;
    const float TWO_LOG2E = 2.f * LOG2E;

    // ---- main loop over all centers ----
    float acc = 0.f;
    #pragma unroll 2
    for (int h = 0; h < H; h++) {
        const ulonglong2* cp = (const ulonglong2*)(c_s + h * D);
        unsigned long long a0 = 0ull, a1 = 0ull, a2 = 0ull, a3 = 0ull;
        #pragma unroll
        for (int j = 0; j < 8; j++) {
            ulonglong2 u = cp[2 * j];
            ulonglong2 v = cp[2 * j + 1];
            ffma2(a0, xr[4 * j + 0], u.x);
            ffma2(a1, xr[4 * j + 1], u.y);
            ffma2(a2, xr[4 * j + 2], v.x);
            ffma2(a3, xr[4 * j + 3], v.y);
        }
        a0 = fadd2(a0, a1);
        a2 = fadd2(a2, a3);
        a0 = fadd2(a0, a2);
        float lo, hi;
        unpack2(a0, lo, hi);
        float dot = lo + hi;
        // exponent in log2 domain: t = (2*dot - x2 - c2) * log2e, clamped <= 0
        float t = fmaf(dot, TWO_LOG2E, -(x2l + c2l_s[h]));
        t = fminf(t, 0.f);
        acc = fmaf(w_s[h], ex2_approx(t), acc);
    }

    out[(size_t)blockIdx.x * ROWS + tid] = acc + bias[0];
}

extern "C" void kernel_launch(void* const* d_in, const int* in_sizes, int n_in,
                              void* d_out, int out_size) {
    const float* X = (const float*)d_in[0];
    const float* C = (const float*)d_in[1];
    const float* w = (const float*)d_in[2];
    const float* b = (const float*)d_in[3];
    float* out = (float*)d_out;

    const int n = in_sizes[0] / D;          // 524288 rows
    const int smem_bytes = (H * D + 2 * H + ROWS * XPAD) * (int)sizeof(float);

    cudaFuncSetAttribute(rbf_svm_kernel,
                         cudaFuncAttributeMaxDynamicSharedMemorySize, smem_bytes);
    rbf_svm_kernel<<<n / ROWS, THREADS, smem_bytes>>>(X, C, w, b, out);
}

// round 4
// speedup vs baseline: 1.3475x; 1.3475x over previous
#include <cuda_runtime.h>

#define D 64
#define H 256
#define BROWS 128            // rows per block
#define THREADS 256          // 16 tx (centers) x 16 ty (row groups)
#define R 8                  // rows per thread
#define KC 16                // k-chunks of 4 floats (D/4)
#define XPLANE 144           // float4 stride per kc plane for X (128 rows + skew room)

__device__ __forceinline__ void ffma2(unsigned long long& d,
                                      unsigned long long a,
                                      unsigned long long b) {
    asm("fma.rn.f32x2 %0, %1, %2, %0;" : "+l"(d) : "l"(a), "l"(b));
}
__device__ __forceinline__ void unpack2(unsigned long long v, float& lo, float& hi) {
    asm("mov.b64 {%0, %1}, %2;" : "=f"(lo), "=f"(hi) : "l"(v));
}
__device__ __forceinline__ float ex2_approx(float x) {
    float r; asm("ex2.approx.f32 %0, %1;" : "=f"(r) : "f"(x)); return r;
}

// X smem addressing: plane per k-chunk, skew rows by (row>>3) float4s so the
// two warp-resident rows (r, r+8) sit 144B apart -> distinct banks.
__device__ __forceinline__ int xidx(int kc, int row) {
    return kc * XPLANE + row + (row >> 3);
}

__global__ void __launch_bounds__(THREADS, 2)
rbf_svm_kernel(const float* __restrict__ X,
               const float* __restrict__ C,
               const float* __restrict__ w,
               const float* __restrict__ bias,
               float* __restrict__ out) {
    extern __shared__ float smem[];
    float4* c4   = (float4*)smem;                    // [KC][H] float4 = 64KB
    float4* x4   = (float4*)(smem + KC * H * 4);     // [KC][XPLANE] float4 = 36KB
    float*  c2l_s = smem + KC * H * 4 + KC * XPLANE * 4;   // H
    float*  w_s   = c2l_s + H;                             // H
    float*  x2l_s = w_s + H;                               // BROWS

    const int tid = threadIdx.x;
    const int tx = tid & 15;
    const int ty = tid >> 4;
    const float LOG2E = 1.4426950408889634f;
    const float TWO_LOG2E = 2.0f * LOG2E;

    // ---- stage C into [kc][h] float4 layout (coalesced gmem reads) ----
    {
        const float4* src = (const float4*)C;
        for (int i = tid; i < H * KC; i += THREADS) {
            float4 v = src[i];
            int h = i >> 4, kc = i & 15;
            c4[kc * H + h] = v;
        }
    }
    // ---- stage X tile into [kc][row(skewed)] float4 layout ----
    {
        const float4* src = (const float4*)(X + (size_t)blockIdx.x * BROWS * D);
        for (int i = tid; i < BROWS * KC; i += THREADS) {
            float4 v = src[i];
            int row = i >> 4, kc = i & 15;
            x4[xidx(kc, row)] = v;
        }
    }
    for (int i = tid; i < H; i += THREADS) w_s[i] = w[i];
    __syncthreads();

    // ---- per-center ||c||^2 * log2e ----
    {
        int h = tid;
        if (h < H) {
            float s = 0.f;
            #pragma unroll
            for (int kc = 0; kc < KC; kc++) {
                float4 v = c4[kc * H + h];
                s = fmaf(v.x, v.x, s); s = fmaf(v.y, v.y, s);
                s = fmaf(v.z, v.z, s); s = fmaf(v.w, v.w, s);
            }
            c2l_s[h] = s * LOG2E;
        }
    }
    // ---- per-row ||x||^2 * log2e ----
    if (tid < BROWS) {
        int row = tid;
        float s = 0.f;
        #pragma unroll
        for (int kc = 0; kc < KC; kc++) {
            float4 v = x4[xidx(kc, row)];
            s = fmaf(v.x, v.x, s); s = fmaf(v.y, v.y, s);
            s = fmaf(v.z, v.z, s); s = fmaf(v.w, v.w, s);
        }
        x2l_s[row] = s * LOG2E;
    }
    __syncthreads();

    const int row0 = ty * R;
    float x2l[R];
    #pragma unroll
    for (int r = 0; r < R; r++) x2l[r] = x2l_s[row0 + r];

    float accr[R];
    #pragma unroll
    for (int r = 0; r < R; r++) accr[r] = 0.f;

    // 4 center tiles; per tile each thread handles centers h = nt*16+tx + cc*64
    for (int nt = 0; nt < 4; nt++) {
        const int hbase = nt * 16 + tx;

        unsigned long long acc2[R][4];
        #pragma unroll
        for (int r = 0; r < R; r++)
            #pragma unroll
            for (int cc = 0; cc < 4; cc++) acc2[r][cc] = 0ull;

        #pragma unroll 2
        for (int kc = 0; kc < KC; kc++) {
            ulonglong2 cv[4];
            #pragma unroll
            for (int cc = 0; cc < 4; cc++)
                cv[cc] = *(const ulonglong2*)&c4[kc * H + hbase + cc * 64];
            #pragma unroll
            for (int r = 0; r < R; r++) {
                ulonglong2 xv = *(const ulonglong2*)&x4[xidx(kc, row0 + r)];
                #pragma unroll
                for (int cc = 0; cc < 4; cc++) {
                    ffma2(acc2[r][cc], xv.x, cv[cc].x);
                    ffma2(acc2[r][cc], xv.y, cv[cc].y);
                }
            }
        }

        // epilogue for this tile: exp in log2 domain, weighted accumulate
        #pragma unroll
        for (int cc = 0; cc < 4; cc++) {
            const int h = hbase + cc * 64;
            const float nc2 = c2l_s[h];
            const float wh  = w_s[h];
            #pragma unroll
            for (int r = 0; r < R; r++) {
                float lo, hi;
                unpack2(acc2[r][cc], lo, hi);
                float dot = lo + hi;
                float t = fmaf(dot, TWO_LOG2E, -(x2l[r] + nc2));
                t = fminf(t, 0.f);
                accr[r] = fmaf(wh, ex2_approx(t), accr[r]);
            }
        }
    }

    // reduce the 16 tx-partials per row within each 16-lane half-warp
    const float b0 = bias[0];
    #pragma unroll
    for (int r = 0; r < R; r++) {
        float v = accr[r];
        v += __shfl_down_sync(0xffffffffu, v, 8, 16);
        v += __shfl_down_sync(0xffffffffu, v, 4, 16);
        v += __shfl_down_sync(0xffffffffu, v, 2, 16);
        v += __shfl_down_sync(0xffffffffu, v, 1, 16);
        if (tx == 0)
            out[(size_t)blockIdx.x * BROWS + row0 + r] = v + b0;
    }
}

extern "C" void kernel_launch(void* const* d_in, const int* in_sizes, int n_in,
                              void* d_out, int out_size) {
    const float* X = (const float*)d_in[0];
    const float* C = (const float*)d_in[1];
    const float* w = (const float*)d_in[2];
    const float* b = (const float*)d_in[3];
    float* out = (float*)d_out;

    const int n = in_sizes[0] / D;   // 524288 rows
    const int smem_bytes = (KC * H * 4 + KC * XPLANE * 4 + 2 * H + BROWS) * (int)sizeof(float);

    cudaFuncSetAttribute(rbf_svm_kernel,
                         cudaFuncAttributeMaxDynamicSharedMemorySize, smem_bytes);
    rbf_svm_kernel<<<n / BROWS, THREADS, smem_bytes>>>(X, C, w, b, out);
}

// round 7
// speedup vs baseline: 2.8891x; 2.1441x over previous
#include <cuda_runtime.h>
#include <cuda_bf16.h>
#include <cstdint>

#define DK 64
#define HN 256
#define TILE_M 128
#define THREADS 256

// precomputed centers (bf16 hi/lo packed pairs) + {c2*log2e, w}
__device__ uint32_t g_Chi[HN * DK / 2];
__device__ uint32_t g_Clo[HN * DK / 2];
__device__ float2   g_cw[HN];

// ---- smem byte offsets from 1024-aligned base ----
#define OFF_BHI 0          // 256x128B bf16-hi centers, swizzled
#define OFF_BLO 32768      // 256x128B bf16-lo centers
#define OFF_AHI 65536      // 128x128B X-hi
#define OFF_ALO 81920      // 128x128B X-lo
#define OFF_CW  98304      // float2[256]
#define OFF_X2  100352     // float[128]  (x2 * log2e)
#define OFF_RED 100864     // float[128][2]
#define SMEM_SZ (101888 + 1024)

#define LOG2E 1.4426950408889634f

static __device__ __forceinline__ uint32_t smem_u32(const void* p) {
    uint32_t a;
    asm("{ .reg .u64 t; cvta.to.shared.u64 t, %1; cvt.u32.u64 %0, t; }" : "=r"(a) : "l"(p));
    return a;
}
static __device__ __forceinline__ float ex2_approx(float x) {
    float r; asm("ex2.approx.f32 %0, %1;" : "=f"(r) : "f"(x)); return r;
}

#define LDSM_X4(r0, r1, r2, r3, addr) \
    asm volatile("ldmatrix.sync.aligned.m8n8.x4.shared.b16 {%0,%1,%2,%3}, [%4];" \
        : "=r"(r0), "=r"(r1), "=r"(r2), "=r"(r3) : "r"(addr))

static __device__ __forceinline__ void mma_bf16(float* c, const uint32_t* a,
                                                uint32_t b0, uint32_t b1) {
    asm volatile(
        "mma.sync.aligned.m16n8k16.row.col.f32.bf16.bf16.f32 "
        "{%0,%1,%2,%3}, {%4,%5,%6,%7}, {%8,%9}, {%0,%1,%2,%3};"
        : "+f"(c[0]), "+f"(c[1]), "+f"(c[2]), "+f"(c[3])
        : "r"(a[0]), "r"(a[1]), "r"(a[2]), "r"(a[3]), "r"(b0), "r"(b1));
}

// split 2 fp32 into packed bf16 hi/lo pairs; accumulate squared norm
static __device__ __forceinline__ void cvt_pair(float a, float b, uint32_t& hi,
                                                uint32_t& lo, float& s2) {
    s2 = fmaf(a, a, s2); s2 = fmaf(b, b, s2);
    __nv_bfloat16 ha = __float2bfloat16_rn(a), hb = __float2bfloat16_rn(b);
    float ra = a - __bfloat162float(ha), rb = b - __bfloat162float(hb);
    __nv_bfloat16 la = __float2bfloat16_rn(ra), lb = __float2bfloat16_rn(rb);
    hi = (uint32_t)__bfloat16_as_ushort(ha) | ((uint32_t)__bfloat16_as_ushort(hb) << 16);
    lo = (uint32_t)__bfloat16_as_ushort(la) | ((uint32_t)__bfloat16_as_ushort(lb) << 16);
}

__global__ void prep_kernel(const float* __restrict__ C, const float* __restrict__ W) {
    const int h = threadIdx.x;              // 256 threads, 1 block
    const float4* cp = (const float4*)(C + h * DK);
    float c2 = 0.f;
    #pragma unroll
    for (int q = 0; q < 16; q++) {
        float4 v = cp[q];
        uint32_t h0, l0, h1, l1;
        cvt_pair(v.x, v.y, h0, l0, c2);
        cvt_pair(v.z, v.w, h1, l1, c2);
        g_Chi[h * 32 + q * 2]     = h0;
        g_Chi[h * 32 + q * 2 + 1] = h1;
        g_Clo[h * 32 + q * 2]     = l0;
        g_Clo[h * 32 + q * 2 + 1] = l1;
    }
    g_cw[h] = make_float2(c2 * LOG2E, W[h]);
}

__global__ void __launch_bounds__(THREADS, 2)
rbf_mma_kernel(const float* __restrict__ X, const float* __restrict__ Bias,
               float* __restrict__ out, int ntiles) {
    extern __shared__ char smem_raw[];
    uint32_t sraw = smem_u32(smem_raw);
    uint32_t sb = (sraw + 1023u) & ~1023u;
    char* sc = smem_raw + (sb - sraw);

    const int tid = threadIdx.x;
    const int warp = tid >> 5, lane = tid & 31;
    const int wm = warp >> 1, wn = warp & 1;          // 4 M-warps x 2 N-warps
    const int g = lane >> 2, qq = lane & 3;
    const float TWO_LOG2E = 2.0f * LOG2E;
    const float b0 = Bias[0];

    float*  x2s  = (float*)(sc + OFF_X2);
    float2* cws  = (float2*)(sc + OFF_CW);
    float*  red  = (float*)(sc + OFF_RED);

    // ---- stage centers (one thread per center row), swizzled chunks ----
    {
        const int h = tid;
        const uint4* hp = (const uint4*)g_Chi + h * 8;
        const uint4* lp = (const uint4*)g_Clo + h * 8;
        #pragma unroll
        for (int q = 0; q < 8; q++) {
            int co = ((q ^ (h & 7)) * 16);
            *(uint4*)(sc + OFF_BHI + h * 128 + co) = hp[q];
            *(uint4*)(sc + OFF_BLO + h * 128 + co) = lp[q];
        }
        cws[h] = g_cw[h];
    }

    for (int t = blockIdx.x; t < ntiles; t += gridDim.x) {
        // ---- stage X tile: thread = half a row ----
        {
            const int row = tid >> 1, half = tid & 1;
            const float4* xp = (const float4*)(X + ((size_t)t * TILE_M + row) * DK + half * 32);
            float s2 = 0.f;
            char* ah = sc + OFF_AHI + row * 128;
            char* al = sc + OFF_ALO + row * 128;
            #pragma unroll
            for (int q = 0; q < 4; q++) {
                float4 v0 = xp[2 * q], v1 = xp[2 * q + 1];
                uint32_t h0, l0, h1, l1, h2, l2, h3, l3;
                cvt_pair(v0.x, v0.y, h0, l0, s2);
                cvt_pair(v0.z, v0.w, h1, l1, s2);
                cvt_pair(v1.x, v1.y, h2, l2, s2);
                cvt_pair(v1.z, v1.w, h3, l3, s2);
                int c = half * 4 + q;
                int co = ((c ^ (row & 7)) * 16);
                *(uint4*)(ah + co) = make_uint4(h0, h1, h2, h3);
                *(uint4*)(al + co) = make_uint4(l0, l1, l2, l3);
            }
            s2 += __shfl_xor_sync(0xffffffffu, s2, 1);
            if (!half) x2s[row] = s2 * LOG2E;
        }
        __syncthreads();

        float rowsum[2][2] = {{0.f, 0.f}, {0.f, 0.f}};   // [mt][row-group]

        #pragma unroll 1
        for (int nc = 0; nc < 4; nc++) {                 // N chunks of 64
            const int hbase = nc * 64 + wn * 32;
            float acc[2][4][4];
            #pragma unroll
            for (int mt = 0; mt < 2; mt++)
                #pragma unroll
                for (int nt = 0; nt < 4; nt++)
                    #pragma unroll
                    for (int k = 0; k < 4; k++) acc[mt][nt][k] = 0.f;

            #pragma unroll
            for (int pass = 0; pass < 3; pass++) {
                const uint32_t abase = sb + (pass == 1 ? OFF_ALO : OFF_AHI);
                const uint32_t bbase = sb + (pass == 2 ? OFF_BLO : OFF_BHI);
                #pragma unroll
                for (int kt = 0; kt < 4; kt++) {
                    uint32_t a[2][4], b[2][4];
                    const int roff = (lane & 7) + ((lane >> 3) & 1) * 8;
                    const int coff = kt * 2 + (lane >> 4);
                    #pragma unroll
                    for (int mt = 0; mt < 2; mt++) {
                        int r = wm * 32 + mt * 16 + roff;
                        uint32_t addr = abase + r * 128 + ((coff ^ (r & 7)) * 16);
                        LDSM_X4(a[mt][0], a[mt][1], a[mt][2], a[mt][3], addr);
                    }
                    #pragma unroll
                    for (int gg = 0; gg < 2; gg++) {
                        int n = hbase + gg * 16 + roff;
                        uint32_t addr = bbase + n * 128 + ((coff ^ (n & 7)) * 16);
                        LDSM_X4(b[gg][0], b[gg][1], b[gg][2], b[gg][3], addr);
                    }
                    #pragma unroll
                    for (int mt = 0; mt < 2; mt++)
                        #pragma unroll
                        for (int nt = 0; nt < 4; nt++) {
                            int gg = nt >> 1, od = nt & 1;
                            mma_bf16(acc[mt][nt], a[mt], b[gg][od], b[gg][od + 2]);
                        }
                }
            }

            // ---- epilogue for this chunk ----
            #pragma unroll
            for (int mt = 0; mt < 2; mt++) {
                const float nx0 = -x2s[wm * 32 + mt * 16 + g];
                const float nx1 = -x2s[wm * 32 + mt * 16 + 8 + g];
                #pragma unroll
                for (int nt = 0; nt < 4; nt++) {
                    const int h = hbase + nt * 8 + qq * 2;
                    const float2 cw0 = cws[h];
                    const float2 cw1 = cws[h + 1];
                    float t00 = fminf(fmaf(acc[mt][nt][0], TWO_LOG2E, nx0 - cw0.x), 0.f);
                    float t01 = fminf(fmaf(acc[mt][nt][1], TWO_LOG2E, nx0 - cw1.x), 0.f);
                    float t10 = fminf(fmaf(acc[mt][nt][2], TWO_LOG2E, nx1 - cw0.x), 0.f);
                    float t11 = fminf(fmaf(acc[mt][nt][3], TWO_LOG2E, nx1 - cw1.x), 0.f);
                    rowsum[mt][0] = fmaf(cw0.y, ex2_approx(t00), rowsum[mt][0]);
                    rowsum[mt][0] = fmaf(cw1.y, ex2_approx(t01), rowsum[mt][0]);
                    rowsum[mt][1] = fmaf(cw0.y, ex2_approx(t10), rowsum[mt][1]);
                    rowsum[mt][1] = fmaf(cw1.y, ex2_approx(t11), rowsum[mt][1]);
                }
            }
        }

        // ---- reduce 4 col-lanes, then the 2 N-warps via smem ----
        #pragma unroll
        for (int mt = 0; mt < 2; mt++)
            #pragma unroll
            for (int rg = 0; rg < 2; rg++) {
                float v = rowsum[mt][rg];
                v += __shfl_xor_sync(0xffffffffu, v, 1);
                v += __shfl_xor_sync(0xffffffffu, v, 2);
                if (qq == 0)
                    red[(wm * 32 + mt * 16 + rg * 8 + g) * 2 + wn] = v;
            }
        __syncthreads();
        if (tid < TILE_M)
            out[(size_t)t * TILE_M + tid] = red[tid * 2] + red[tid * 2 + 1] + b0;
    }
}

extern "C" void kernel_launch(void* const* d_in, const int* in_sizes, int n_in,
                              void* d_out, int out_size) {
    const float* X = (const float*)d_in[0];
    const float* C = (const float*)d_in[1];
    const float* w = (const float*)d_in[2];
    const float* b = (const float*)d_in[3];
    float* out = (float*)d_out;

    const int ntiles = in_sizes[0] / (DK * TILE_M);   // 4096
    int dev = 0, sms = 148;
    cudaGetDevice(&dev);
    cudaDeviceGetAttribute(&sms, cudaDevAttrMultiProcessorCount, dev);
    int grid = 2 * sms;
    if (grid > ntiles) grid = ntiles;

    prep_kernel<<<1, HN>>>(C, w);
    cudaFuncSetAttribute(rbf_mma_kernel,
                         cudaFuncAttributeMaxDynamicSharedMemorySize, SMEM_SZ);
    rbf_mma_kernel<<<grid, THREADS, SMEM_SZ>>>(X, b, out, ntiles);
}